// round 6
// baseline (speedup 1.0000x reference)
#include <cuda_runtime.h>
#include <cuda_bf16.h>
#include <float.h>

// BinsChamferLoss, single fused kernel (R6: LUT-hint search, O(1) per target).
// sum over (b,p) of min_t | center(b,p) - target(b,t) |, targets masked to 0 below 0.001.
//
// Encodings (targets >= 0 -> float bits order-isomorphic to u32):
//   maxBelow: enc = bits(t) + 1   (u32 atomicMax; 0 = none)
//   minAbove: enc = ~bits(t)      (u32 atomicMax == min over t; 0 = none)

#define MAXB 32
#define P_BINS 256
#define MIN_DEPTH 0.001f
#define LUTN 1024

__device__ unsigned int g_maxBelow[MAXB * P_BINS];   // zero-init = "none"
__device__ unsigned int g_minAbove[MAXB * P_BINS];   // zero-init = "none"
__device__ float        g_batchSum[MAXB];
__device__ unsigned int g_cnt[MAXB];
__device__ unsigned int g_done;

__global__ void __launch_bounds__(P_BINS)
k_fused(const float* __restrict__ bins, const float* __restrict__ depth,
        int M, int B, float* __restrict__ out)
{
    const int b    = blockIdx.y;
    const int tid  = threadIdx.x;
    const int lane = tid & 31;
    const int warp = tid >> 5;

    __shared__ float         sC[P_BINS];
    __shared__ unsigned int  sA[P_BINS];
    __shared__ unsigned int  sS[P_BINS];
    __shared__ unsigned short sLUT[LUTN];
    __shared__ unsigned int  wA[8], wS[8];
    __shared__ float         wsum[8];
    __shared__ int           sFinisher;

    // ---- Phase 1: centers + register bitonic sort (shfl for j<32) ----
    float v;
    {
        const float* bb = bins + b * (P_BINS + 1);
        v = 0.5f * (bb[tid] + bb[tid + 1]);
        sA[tid] = 0u;
        sS[tid] = 0u;
    }

#pragma unroll
    for (int k = 2; k <= P_BINS; k <<= 1) {
#pragma unroll
        for (int j = k >> 1; j >= 1; j >>= 1) {
            bool up = ((tid & k) == 0);
            float other;
            if (j >= 32) {
                __syncthreads();
                sC[tid] = v;
                __syncthreads();
                other = sC[tid ^ j];
            } else {
                other = __shfl_xor_sync(0xffffffffu, v, j);
            }
            bool lower = ((tid & j) == 0);
            v = (lower == up) ? fminf(v, other) : fmaxf(v, other);
        }
    }
    __syncthreads();
    sC[tid] = v;
    __syncthreads();

    // ---- Phase 1b: build LUT hint (plain stores, ranges partition [0,LUTN)) ----
    const float cmin = sC[0];
    const float cmax = sC[P_BINS - 1];
    const float span = cmax - cmin;
    const float invw = (span > 0.0f) ? ((float)LUTN / span) : 0.0f;
    {
        // start(tid) monotone non-decreasing in tid
        float me = sC[tid];
        int st = min(LUTN, max(0, (int)((me - cmin) * invw)));
        int en;
        if (tid == P_BINS - 1) en = LUTN;
        else {
            float nx = sC[tid + 1];
            en = min(LUTN, max(0, (int)((nx - cmin) * invw)));
        }
        if (tid == 0) st = 0;
        for (int k = st; k < en; ++k) sLUT[k] = (unsigned short)tid;
    }
    __syncthreads();

    // ---- Phase 2: scatter (each thread: exactly one float4 slot, guarded) ----
    {
        const float4* tgt4 = (const float4*)(depth + (long long)b * M);
        const int M4 = M >> 2;                       // M % 4 == 0
        const int i = blockIdx.x * blockDim.x + tid;
        if (i < M4) {
            float4 vv = tgt4[i];
            float vals[4] = {vv.x, vv.y, vv.z, vv.w};
#pragma unroll
            for (int q = 0; q < 4; ++q) {
                float t = vals[q];
                t = (t >= MIN_DEPTH) ? t : 0.0f;
                unsigned int tb = __float_as_uint(t);

                // LUT hint -> exact lower_bound via bidirectional walk
                int k = min(LUTN - 1, max(0, (int)((t - cmin) * invw)));
                int base = (int)sLUT[k];
                while (base > 0      && sC[base - 1] >= t) --base;
                while (base < P_BINS && sC[base]     <  t) ++base;
                // base == lower_bound(sC, t)

                if (base < P_BINS) atomicMax(&sA[base], tb + 1u);

                // upper_bound via tie-walk (ties ~never; stays exact)
                int ub = base;
                while (ub < P_BINS && sC[ub] == t) ++ub;
                if (ub > 0) atomicMax(&sS[ub - 1], ~tb);
            }
        }
    }
    __syncthreads();

    // ---- Phase 3: flush to global scratch ----
    {
        unsigned int a = sA[tid], s = sS[tid];
        if (a) atomicMax(&g_maxBelow[b * P_BINS + tid], a);
        if (s) atomicMax(&g_minAbove[b * P_BINS + tid], s);
    }

    // ---- Phase 4: last block of this batch reduces it ----
    __threadfence();
    if (tid == 0) {
        unsigned int old = atomicAdd(&g_cnt[b], 1u);
        sFinisher = (old == (unsigned)(gridDim.x - 1));
    }
    __syncthreads();
    if (!sFinisher) return;
    __threadfence();   // acquire all batch-b flushes

    unsigned int encA = atomicMax(&g_maxBelow[b * P_BINS + tid], 0u);
    unsigned int encS = atomicMax(&g_minAbove[b * P_BINS + tid], 0u);
    g_maxBelow[b * P_BINS + tid] = 0u;     // reset for graph replay
    g_minAbove[b * P_BINS + tid] = 0u;
    if (tid == 0) g_cnt[b] = 0u;

    // prefix-max scan over encA (tid order), shuffle-based
    unsigned int pv = encA;
#pragma unroll
    for (int o = 1; o < 32; o <<= 1) {
        unsigned int n = __shfl_up_sync(0xffffffffu, pv, o);
        if (lane >= o) pv = max(pv, n);
    }
    if (lane == 31) wA[warp] = pv;

    // suffix-max scan over encS, shuffle-based
    unsigned int sv = encS;
#pragma unroll
    for (int o = 1; o < 32; o <<= 1) {
        unsigned int n = __shfl_down_sync(0xffffffffu, sv, o);
        if (lane + o < 32) sv = max(sv, n);
    }
    if (lane == 0) wS[warp] = sv;
    __syncthreads();

    unsigned int offA = 0u, offS = 0u;
    for (int w = 0; w < warp; ++w)     offA = max(offA, wA[w]);
    for (int w = warp + 1; w < 8; ++w) offS = max(offS, wS[w]);
    pv = max(pv, offA);
    sv = max(sv, offS);

    float c   = sC[tid];
    float dLo = pv ? (c - __uint_as_float(pv - 1u)) : FLT_MAX;
    float dHi = sv ? (__uint_as_float(~sv) - c)     : FLT_MAX;
    float d   = fminf(dLo, dHi);

#pragma unroll
    for (int o = 16; o >= 1; o >>= 1) d += __shfl_down_sync(0xffffffffu, d, o);
    if (lane == 0) wsum[warp] = d;
    __syncthreads();

    if (tid == 0) {
        float s = 0.0f;
        for (int w = 0; w < 8; ++w) s += wsum[w];
        g_batchSum[b] = s;

        __threadfence();
        unsigned int old = atomicAdd(&g_done, 1u);
        if (old == (unsigned)(B - 1)) {
            __threadfence();
            float tot = 0.0f;
            for (int i = 0; i < B; ++i) tot += g_batchSum[i];
            out[0] = tot;
            g_done = 0u;
        }
    }
}

extern "C" void kernel_launch(void* const* d_in, const int* in_sizes, int n_in,
                              void* d_out, int out_size)
{
    int bi = 0, di = 1;
    if (n_in >= 2 && in_sizes[0] > in_sizes[1]) { bi = 1; di = 0; }
    const float* bins  = (const float*)d_in[bi];
    const float* depth = (const float*)d_in[di];

    const int B = in_sizes[bi] / (P_BINS + 1);
    const int M = in_sizes[di] / B;

    // One float4 per thread in the scatter phase.
    const int M4 = M >> 2;
    const int splits = (M4 + P_BINS - 1) / P_BINS;   // 75 for 320x240

    dim3 grid(splits, B);
    k_fused<<<grid, P_BINS>>>(bins, depth, M, B, (float*)d_out);
}